// round 6
// baseline (speedup 1.0000x reference)
#include <cuda_runtime.h>
#include <stdint.h>

#define BB 16
#define NN 4096
#define DD 32
#define CC 64
#define KK 16
#define TS 512
#define TST 516        // padded row stride (floats); 516*4=2064 bytes, 16B-aligned
#define NTILES (NN / TS)
#define THREADS 128
#define WARPS 4
#define QPC 256        // queries per CTA (2 per lane)

typedef unsigned long long u64;
typedef unsigned int u32;

#define SMEM_T_BYTES   (DD * TST * 4)
#define SMEM_RC_BYTES  (TS * 4)
#define SMEM_IDX_BYTES (WARPS * 64 * KK * 4)
#define SMEM_TOTAL     (SMEM_T_BYTES + SMEM_RC_BYTES + SMEM_IDX_BYTES)

__device__ float g_norms[BB * NN];   // precomputed candidate squared norms

__device__ __forceinline__ u64 pk2(float a, float b) {
    u64 r; asm("mov.b64 %0, {%1,%2};" : "=l"(r) : "f"(a), "f"(b)); return r;
}
__device__ __forceinline__ u64 fma2(u64 a, u64 b, u64 c) {
    u64 d; asm("fma.rn.f32x2 %0, %1, %2, %3;" : "=l"(d) : "l"(a), "l"(b), "l"(c));
    return d;
}
__device__ __forceinline__ void up2(u64 v, float& a, float& b) {
    asm("mov.b64 {%0,%1}, %2;" : "=f"(a), "=f"(b) : "l"(v));
}

// Balanced binary tree sum, XLA warp-shfl grouping (stride 16,8,4,2,1).
__device__ __forceinline__ float tree32(float t[32]) {
    #pragma unroll
    for (int off = 16; off >= 1; off >>= 1)
        #pragma unroll
        for (int i = 0; i < off; ++i)
            t[i] = __fadd_rn(t[i], t[i + off]);
    return t[0];
}

// Branch-free insert into ascending sorted k[0..15]; inserting UINT64_MAX is a no-op.
__device__ __forceinline__ void ins16(u64 (&k)[KK], u64 nk) {
    #pragma unroll
    for (int s = KK - 1; s >= 1; --s) {
        u64 mn = (nk < k[s]) ? nk : k[s];
        k[s] = (k[s-1] > mn) ? k[s-1] : mn;
    }
    k[0] = (nk < k[0]) ? nk : k[0];
}

// threshold distance (float) from the worst kept key; sentinel -> +inf
__device__ __forceinline__ float thr_of(u64 wk) {
    u32 hi = (u32)(wk >> 32) ^ 0x80000000u;
    hi = hi < 0x7f800000u ? hi : 0x7f800000u;
    return __uint_as_float(hi);
}

__global__ void norms_kernel(const float* __restrict__ points) {
    int idx = blockIdx.x * blockDim.x + threadIdx.x;   // one row per thread
    if (idx >= BB * NN) return;
    const float4* cp = (const float4*)(points + (size_t)idx * DD);
    float x[DD];
    #pragma unroll
    for (int j4 = 0; j4 < DD / 4; ++j4) {
        float4 v = __ldg(cp + j4);
        x[j4*4+0] = __fmul_rn(v.x, v.x);
        x[j4*4+1] = __fmul_rn(v.y, v.y);
        x[j4*4+2] = __fmul_rn(v.z, v.z);
        x[j4*4+3] = __fmul_rn(v.w, v.w);
    }
    g_norms[idx] = tree32(x);
}

// Per-query selection epilogue over a 16-candidate block. Q selects which
// accumulator halves belong to this query (compile-time -> arrays stay in regs).
template<int Q>
__device__ __forceinline__ void epilogue16(
    const u64 (&acc)[16], const float (&rc)[16],
    float rqv, int nqv, int gi,
    u64 (&kq)[KK], u64 (&bq)[4], float& wq, int& cq)
{
    const unsigned FULL = 0xffffffffu;
    float d[16];
    #pragma unroll
    for (int p = 0; p < 8; ++p) {
        float a, b_;
        up2(acc[2*p + Q], a, b_);
        // D = fl(fl(rq - 2m) + rc); FFMA(-2,m,rq) == fl(rq - fl(2m)) bitwise
        d[2*p]   = __fadd_rn(__fmaf_rn(-2.f, a,  rqv), rc[2*p]);
        d[2*p+1] = __fadd_rn(__fmaf_rn(-2.f, b_, rqv), rc[2*p+1]);
    }
    int cnt = 0;
    #pragma unroll
    for (int t = 0; t < 16; ++t) cnt += (d[t] <= wq) ? 1 : 0;

    if (__any_sync(FULL, cnt > 0)) {
        if (__any_sync(FULL, cq + cnt > 4)) {
            ins16(kq, bq[0]); ins16(kq, bq[1]); ins16(kq, bq[2]); ins16(kq, bq[3]);
            bq[0] = bq[1] = bq[2] = bq[3] = ~0ull;
            cq = 0;
            wq = thr_of(kq[KK-1]);
        }
        if (__any_sync(FULL, cnt > 4)) {
            // bootstrap-ish path (early candidates): direct exact inserts
            #pragma unroll
            for (int t = 0; t < 16; ++t) {
                bool ps = d[t] <= wq;
                int ci = gi + t;
                u32 h = __float_as_uint(d[t]) | 0x80000000u;
                u64 kv = ((u64)h << 32) | (u32)ci;
                kv = (ci == nqv || !ps) ? ~0ull : kv;
                ins16(kq, kv);
            }
            wq = thr_of(kq[KK-1]);
        } else {
            // common armed path: 4-deep shift buffer, exact keys
            #pragma unroll
            for (int t = 0; t < 16; ++t) {
                bool ps = d[t] <= wq;
                int ci = gi + t;
                u32 h = __float_as_uint(d[t]) | 0x80000000u;
                u64 kv = ((u64)h << 32) | (u32)ci;
                kv = (ci == nqv) ? ~0ull : kv;
                bq[3] = ps ? bq[2] : bq[3];
                bq[2] = ps ? bq[1] : bq[2];
                bq[1] = ps ? bq[0] : bq[1];
                bq[0] = ps ? kv    : bq[0];
                cq += ps ? 1 : 0;
            }
        }
    }
}

__global__ __launch_bounds__(THREADS, 2)
void knn_select_kernel(const float* __restrict__ points,
                       const float* __restrict__ features,
                       float* __restrict__ out)
{
    extern __shared__ char smem_raw[];
    float (*s_t)[TST] = (float(*)[TST])smem_raw;
    float* s_rc = (float*)(smem_raw + SMEM_T_BYTES);
    int* s_idx = (int*)(smem_raw + SMEM_T_BYTES + SMEM_RC_BYTES); // [WARPS][64][KK]

    const int lane = threadIdx.x & 31;
    const int warp = threadIdx.x >> 5;
    const int b    = blockIdx.x >> 4;            // 16 CTAs per batch
    const int q0b  = (blockIdx.x & 15) * QPC;
    const int nq0  = q0b + warp * 32 + lane;
    const int nq1  = nq0 + 128;

    const float* pb = points   + (size_t)b * NN * DD;
    const float* fb = features + (size_t)b * NN * CC;

    // ---- both query points into scalar registers + rq (tree32, reference order) ----
    float qs0[DD], qs1[DD], rq0, rq1;
    {
        float x[DD];
        const float4* qp = (const float4*)(pb + (size_t)nq0 * DD);
        #pragma unroll
        for (int j4 = 0; j4 < DD / 4; ++j4) {
            float4 v = __ldg(qp + j4);
            qs0[j4*4+0] = v.x; qs0[j4*4+1] = v.y; qs0[j4*4+2] = v.z; qs0[j4*4+3] = v.w;
            x[j4*4+0] = __fmul_rn(v.x, v.x); x[j4*4+1] = __fmul_rn(v.y, v.y);
            x[j4*4+2] = __fmul_rn(v.z, v.z); x[j4*4+3] = __fmul_rn(v.w, v.w);
        }
        rq0 = tree32(x);
        qp = (const float4*)(pb + (size_t)nq1 * DD);
        #pragma unroll
        for (int j4 = 0; j4 < DD / 4; ++j4) {
            float4 v = __ldg(qp + j4);
            qs1[j4*4+0] = v.x; qs1[j4*4+1] = v.y; qs1[j4*4+2] = v.z; qs1[j4*4+3] = v.w;
            x[j4*4+0] = __fmul_rn(v.x, v.x); x[j4*4+1] = __fmul_rn(v.y, v.y);
            x[j4*4+2] = __fmul_rn(v.z, v.z); x[j4*4+3] = __fmul_rn(v.w, v.w);
        }
        rq1 = tree32(x);
    }

    u64 k0[KK], k1[KK], bf0[4], bf1[4];
    #pragma unroll
    for (int i = 0; i < KK; ++i) { k0[i] = ~0ull; k1[i] = ~0ull; }
    bf0[0]=bf0[1]=bf0[2]=bf0[3]=~0ull;
    bf1[0]=bf1[1]=bf1[2]=bf1[3]=~0ull;
    float wdf0 = __int_as_float(0x7f800000), wdf1 = __int_as_float(0x7f800000);
    int count0 = 0, count1 = 0;

    for (int tile = 0; tile < NTILES; ++tile) {
        __syncthreads();
        {
            const float4* src = (const float4*)(pb + (size_t)tile * TS * DD);
            #pragma unroll
            for (int it = 0; it < (TS * DD / 4) / THREADS; ++it) {   // 32
                int v  = threadIdx.x + it * THREADS;
                int c  = v >> 3;
                int j0 = (v & 7) << 2;
                float4 p4 = src[v];
                s_t[j0+0][c] = p4.x;
                s_t[j0+1][c] = p4.y;
                s_t[j0+2][c] = p4.z;
                s_t[j0+3][c] = p4.w;
            }
            // tile candidate norms (precomputed): 128 threads x 1 float4 = 512
            *(float4*)&s_rc[threadIdx.x * 4] =
                *(const float4*)&g_norms[b * NN + tile * TS + threadIdx.x * 4];
        }
        __syncthreads();

        #pragma unroll 1
        for (int c16 = 0; c16 < TS; c16 += 16) {
            // ---- 16 candidates x 2 queries: 16 packed FMA chains (ascending j) ----
            u64 acc[16];
            #pragma unroll
            for (int i = 0; i < 16; ++i) acc[i] = 0ull;
            #pragma unroll
            for (int j = 0; j < DD; ++j) {
                u64 q0j = pk2(qs0[j], qs0[j]);
                u64 q1j = pk2(qs1[j], qs1[j]);
                const ulonglong2* row = (const ulonglong2*)&s_t[j][c16];
                ulonglong2 pA = row[0], pB = row[1], pC = row[2], pD = row[3];
                acc[0]  = fma2(q0j, pA.x, acc[0]);
                acc[1]  = fma2(q1j, pA.x, acc[1]);
                acc[2]  = fma2(q0j, pA.y, acc[2]);
                acc[3]  = fma2(q1j, pA.y, acc[3]);
                acc[4]  = fma2(q0j, pB.x, acc[4]);
                acc[5]  = fma2(q1j, pB.x, acc[5]);
                acc[6]  = fma2(q0j, pB.y, acc[6]);
                acc[7]  = fma2(q1j, pB.y, acc[7]);
                acc[8]  = fma2(q0j, pC.x, acc[8]);
                acc[9]  = fma2(q1j, pC.x, acc[9]);
                acc[10] = fma2(q0j, pC.y, acc[10]);
                acc[11] = fma2(q1j, pC.y, acc[11]);
                acc[12] = fma2(q0j, pD.x, acc[12]);
                acc[13] = fma2(q1j, pD.x, acc[13]);
                acc[14] = fma2(q0j, pD.y, acc[14]);
                acc[15] = fma2(q1j, pD.y, acc[15]);
            }
            const int gi = tile * TS + c16;
            float rc[16];
            {
                float4 r0 = *(const float4*)&s_rc[c16];
                float4 r1 = *(const float4*)&s_rc[c16 + 4];
                float4 r2 = *(const float4*)&s_rc[c16 + 8];
                float4 r3 = *(const float4*)&s_rc[c16 + 12];
                rc[0]=r0.x; rc[1]=r0.y; rc[2]=r0.z; rc[3]=r0.w;
                rc[4]=r1.x; rc[5]=r1.y; rc[6]=r1.z; rc[7]=r1.w;
                rc[8]=r2.x; rc[9]=r2.y; rc[10]=r2.z; rc[11]=r2.w;
                rc[12]=r3.x; rc[13]=r3.y; rc[14]=r3.z; rc[15]=r3.w;
            }
            epilogue16<0>(acc, rc, rq0, nq0, gi, k0, bf0, wdf0, count0);
            epilogue16<1>(acc, rc, rq1, nq1, gi, k1, bf1, wdf1, count1);
        }
    }

    // final flush
    ins16(k0, bf0[0]); ins16(k0, bf0[1]); ins16(k0, bf0[2]); ins16(k0, bf0[3]);
    ins16(k1, bf1[0]); ins16(k1, bf1[1]); ins16(k1, bf1[2]); ins16(k1, bf1[3]);

    // k sorted ascending by (dist, idx) = reference neighbor order
    #pragma unroll
    for (int kk = 0; kk < KK; ++kk) {
        s_idx[(warp * 64 + lane) * KK + kk]      = (int)(u32)k0[kk];
        s_idx[(warp * 64 + 32 + lane) * KK + kk] = (int)(u32)k1[kk];
    }
    __syncwarp();

    // ---- gather + write: warp iterates its 64 queries, lanes split channels ----
    for (int qq = 0; qq < 64; ++qq) {
        int n = q0b + warp * 32 + (qq & 31) + ((qq >> 5) << 7);
        float c0 = fb[(size_t)n * CC + lane];
        float c1 = fb[(size_t)n * CC + lane + 32];
        float* ob = out + (size_t)(b * NN + n) * KK * (2 * CC);
        #pragma unroll
        for (int kk = 0; kk < KK; ++kk) {
            int nbv = s_idx[(warp * 64 + qq) * KK + kk];
            const float* fr = fb + (size_t)nbv * CC;
            float g0 = __ldg(fr + lane);
            float g1 = __ldg(fr + lane + 32);
            float* orow = ob + kk * (2 * CC);
            __stcs(orow + lane,      g0);
            __stcs(orow + 32 + lane, g1);
            __stcs(orow + 64 + lane, g0 - c0);
            __stcs(orow + 96 + lane, g1 - c1);
        }
    }
}

extern "C" void kernel_launch(void* const* d_in, const int* in_sizes, int n_in,
                              void* d_out, int out_size) {
    const float* points   = (const float*)d_in[0];
    const float* features = (const float*)d_in[1];
    float* out = (float*)d_out;
    (void)in_sizes; (void)n_in; (void)out_size;
    cudaFuncSetAttribute(knn_select_kernel,
                         cudaFuncAttributeMaxDynamicSharedMemorySize, SMEM_TOTAL);
    norms_kernel<<<(BB * NN + 255) / 256, 256>>>(points);
    knn_select_kernel<<<BB * (NN / QPC), THREADS, SMEM_TOTAL>>>(points, features, out);
}

// round 7
// speedup vs baseline: 2.0460x; 2.0460x over previous
#include <cuda_runtime.h>
#include <stdint.h>

#define BB 16
#define NN 4096
#define DD 32
#define CC 64
#define KK 16
#define TS 256
#define TST 260       // padded row stride (floats); 1040B, 16B-aligned
#define NTILES (NN / TS)
#define THREADS 128
#define WARPS 4
#define CAP 20        // per-lane stack capacity (u64 entries)

typedef unsigned long long u64;
typedef unsigned int u32;

// dynamic smem layout (bytes)
#define SZ_T       (DD * TST * 4)          // 33280
#define SZ_RC      (TS * 4)                // 1024
#define SZ_STK_W   (CAP * 32 * 8)          // 5120 per warp
#define OFF_RC     SZ_T
#define OFF_STK    (SZ_T + SZ_RC)
#define SMEM_TOTAL (OFF_STK + WARPS * SZ_STK_W)   // 54784

__device__ float g_norms[BB * NN];

__device__ __forceinline__ u64 pk2(float a, float b) {
    u64 r; asm("mov.b64 %0, {%1,%2};" : "=l"(r) : "f"(a), "f"(b)); return r;
}
__device__ __forceinline__ u64 fma2(u64 a, u64 b, u64 c) {
    u64 d; asm("fma.rn.f32x2 %0, %1, %2, %3;" : "=l"(d) : "l"(a), "l"(b), "l"(c));
    return d;
}
__device__ __forceinline__ void up2(u64 v, float& a, float& b) {
    asm("mov.b64 {%0,%1}, %2;" : "=f"(a), "=f"(b) : "l"(v));
}

// Balanced binary tree sum, XLA warp-shfl grouping (stride 16,8,4,2,1).
__device__ __forceinline__ float tree32(float t[32]) {
    #pragma unroll
    for (int off = 16; off >= 1; off >>= 1)
        #pragma unroll
        for (int i = 0; i < off; ++i)
            t[i] = __fadd_rn(t[i], t[i + off]);
    return t[0];
}

// Branch-free insert into ascending sorted k[0..15]; UINT64_MAX is a no-op.
__device__ __forceinline__ void ins16(u64 (&k)[KK], u64 nk) {
    #pragma unroll
    for (int s = KK - 1; s >= 1; --s) {
        u64 mn = (nk < k[s]) ? nk : k[s];
        k[s] = (k[s-1] > mn) ? k[s-1] : mn;
    }
    k[0] = (nk < k[0]) ? nk : k[0];
}

// threshold distance (float) from the worst kept key; sentinel -> +inf
__device__ __forceinline__ float thr_of(u64 wk) {
    u32 hi = (u32)(wk >> 32) ^ 0x80000000u;
    hi = hi < 0x7f800000u ? hi : 0x7f800000u;
    return __uint_as_float(hi);
}

__global__ void norms_kernel(const float* __restrict__ points) {
    int idx = blockIdx.x * blockDim.x + threadIdx.x;
    if (idx >= BB * NN) return;
    const float4* cp = (const float4*)(points + (size_t)idx * DD);
    float x[DD];
    #pragma unroll
    for (int j4 = 0; j4 < DD / 4; ++j4) {
        float4 v = __ldg(cp + j4);
        x[j4*4+0] = __fmul_rn(v.x, v.x);
        x[j4*4+1] = __fmul_rn(v.y, v.y);
        x[j4*4+2] = __fmul_rn(v.z, v.z);
        x[j4*4+3] = __fmul_rn(v.w, v.w);
    }
    g_norms[idx] = tree32(x);
}

// Drain this lane's stack entries into the sorted top-16 (warp-uniform trip count).
__device__ __forceinline__ void drain(u64* stk, int lane, int& cnt,
                                      u64 (&k)[KK], float& wq) {
    int mx = __reduce_max_sync(0xffffffffu, (unsigned)cnt);
    for (int e = 0; e < mx; ++e) {
        u64 v = (e < cnt) ? stk[e * 32 + lane] : ~0ull;
        ins16(k, v);
    }
    cnt = 0;
    wq = thr_of(k[KK - 1]);
}

__global__ __launch_bounds__(THREADS, 4)
void knn_select_kernel(const float* __restrict__ points,
                       const float* __restrict__ features,
                       float* __restrict__ out)
{
    extern __shared__ char smem_raw[];
    float (*s_t)[TST] = (float(*)[TST])smem_raw;
    float* s_rc = (float*)(smem_raw + OFF_RC);

    const int lane = threadIdx.x & 31;
    const int warp = threadIdx.x >> 5;
    const int b    = blockIdx.x >> 5;            // 32 CTAs per batch
    const int q0b  = (blockIdx.x & 31) * THREADS;
    const int nq   = q0b + warp * 32 + lane;

    u64* stk = (u64*)(smem_raw + OFF_STK + warp * SZ_STK_W);

    const float* pb = points   + (size_t)b * NN * DD;
    const float* fb = features + (size_t)b * NN * CC;

    // ---- query point into scalar registers + rq (tree32, reference order) ----
    float qs[DD], rq;
    {
        float x[DD];
        const float4* qp = (const float4*)(pb + (size_t)nq * DD);
        #pragma unroll
        for (int j4 = 0; j4 < DD / 4; ++j4) {
            float4 v = __ldg(qp + j4);
            qs[j4*4+0] = v.x; qs[j4*4+1] = v.y; qs[j4*4+2] = v.z; qs[j4*4+3] = v.w;
            x[j4*4+0] = __fmul_rn(v.x, v.x); x[j4*4+1] = __fmul_rn(v.y, v.y);
            x[j4*4+2] = __fmul_rn(v.z, v.z); x[j4*4+3] = __fmul_rn(v.w, v.w);
        }
        rq = tree32(x);
    }

    u64 k[KK];
    #pragma unroll
    for (int i = 0; i < KK; ++i) k[i] = ~0ull;
    float wq = __int_as_float(0x7f800000);       // +inf
    int cnt = 0;

    const unsigned FULL = 0xffffffffu;

    for (int tile = 0; tile < NTILES; ++tile) {
        __syncthreads();
        {
            const float4* src = (const float4*)(pb + (size_t)tile * TS * DD);
            #pragma unroll
            for (int it = 0; it < (TS * DD / 4) / THREADS; ++it) {   // 16
                int v  = threadIdx.x + it * THREADS;
                int c  = v >> 3;
                int j0 = (v & 7) << 2;
                float4 p4 = src[v];
                s_t[j0+0][c] = p4.x;
                s_t[j0+1][c] = p4.y;
                s_t[j0+2][c] = p4.z;
                s_t[j0+3][c] = p4.w;
            }
            if (threadIdx.x < TS / 4)
                *(float4*)&s_rc[threadIdx.x * 4] =
                    *(const float4*)&g_norms[b * NN + tile * TS + threadIdx.x * 4];
        }
        __syncthreads();

        #pragma unroll 1
        for (int c16 = 0; c16 < TS; c16 += 16) {
            // ---- 16 candidates: 8 packed FMA chains (ascending j, exact) ----
            u64 acc[8];
            #pragma unroll
            for (int i = 0; i < 8; ++i) acc[i] = 0ull;
            #pragma unroll
            for (int j = 0; j < DD; ++j) {
                u64 qj = pk2(qs[j], qs[j]);
                const ulonglong2* row = (const ulonglong2*)&s_t[j][c16];
                ulonglong2 pA = row[0], pB = row[1], pC = row[2], pD = row[3];
                acc[0] = fma2(qj, pA.x, acc[0]);
                acc[1] = fma2(qj, pA.y, acc[1]);
                acc[2] = fma2(qj, pB.x, acc[2]);
                acc[3] = fma2(qj, pB.y, acc[3]);
                acc[4] = fma2(qj, pC.x, acc[4]);
                acc[5] = fma2(qj, pC.y, acc[5]);
                acc[6] = fma2(qj, pD.x, acc[6]);
                acc[7] = fma2(qj, pD.y, acc[7]);
            }
            const int gi = tile * TS + c16;

            // D = fl(fl(rq - 2m) + rc); FFMA(-2,m,rq) == fl(rq - fl(2m)) bitwise
            float d[16];
            #pragma unroll
            for (int p = 0; p < 8; ++p) {
                float a, b_;
                up2(acc[p], a, b_);
                d[2*p]   = __fadd_rn(__fmaf_rn(-2.f, a,  rq), s_rc[c16 + 2*p]);
                d[2*p+1] = __fadd_rn(__fmaf_rn(-2.f, b_, rq), s_rc[c16 + 2*p+1]);
            }

            bool ps[16]; bool any = false;
            #pragma unroll
            for (int t = 0; t < 16; ++t) {
                ps[t] = (d[t] <= wq) && (gi + t != nq);
                any |= ps[t];
            }

            if (__any_sync(FULL, any)) {
                // straight-line predicated stack pushes (exact keys)
                #pragma unroll
                for (int t = 0; t < 16; ++t) {
                    if (ps[t]) {
                        u32 h = __float_as_uint(d[t]) | 0x80000000u;
                        stk[cnt * 32 + lane] = ((u64)h << 32) | (u32)(gi + t);
                        ++cnt;
                    }
                }
                if (__any_sync(FULL, cnt > CAP - 16))
                    drain(stk, lane, cnt, k, wq);
            }
        }
    }

    // final drain; k[0..15] sorted ascending by (dist, idx) = reference order
    drain(stk, lane, cnt, k, wq);

    // publish indices into this warp's (now dead) stack region
    int* si = (int*)stk;
    #pragma unroll
    for (int kk = 0; kk < KK; ++kk) si[lane * KK + kk] = (int)(u32)k[kk];
    __syncwarp();

    // ---- gather + write: 2 contiguous channels per lane, 64-bit accesses ----
    const int l2 = lane * 2;
    for (int qq = 0; qq < 32; ++qq) {
        int n = q0b + warp * 32 + qq;
        float2 c = *(const float2*)(fb + (size_t)n * CC + l2);
        float* ob = out + (size_t)(b * NN + n) * KK * (2 * CC);
        #pragma unroll
        for (int kk = 0; kk < KK; ++kk) {
            int nbv = si[qq * KK + kk];
            float2 g = *(const float2*)(fb + (size_t)nbv * CC + l2);
            float* orow = ob + kk * (2 * CC);
            __stcs((float2*)(orow + l2), g);
            __stcs((float2*)(orow + 64 + l2), make_float2(g.x - c.x, g.y - c.y));
        }
    }
}

extern "C" void kernel_launch(void* const* d_in, const int* in_sizes, int n_in,
                              void* d_out, int out_size) {
    const float* points   = (const float*)d_in[0];
    const float* features = (const float*)d_in[1];
    float* out = (float*)d_out;
    (void)in_sizes; (void)n_in; (void)out_size;
    cudaFuncSetAttribute(knn_select_kernel,
                         cudaFuncAttributeMaxDynamicSharedMemorySize, SMEM_TOTAL);
    norms_kernel<<<(BB * NN + 255) / 256, 256>>>(points);
    knn_select_kernel<<<BB * (NN / THREADS), THREADS, SMEM_TOTAL>>>(points, features, out);
}

// round 8
// speedup vs baseline: 2.5341x; 1.2385x over previous
#include <cuda_runtime.h>
#include <stdint.h>

#define BB 16
#define NN 4096
#define DD 32
#define CC 64
#define KK 16
#define TS 256
#define TST 260       // padded row stride (floats); 1040B, 16B-aligned
#define NTILES (NN / TS)
#define THREADS 128
#define WARPS 4
#define QPC 256       // queries per CTA (2 per lane)
#define CAP 16        // per-lane stack depth per query

typedef unsigned long long u64;
typedef unsigned int u32;

// dynamic smem layout (bytes)
#define SZ_T     (DD * TST * 4)          // 33280
#define SZ_RC    (TS * 4)                // 1024
#define SZ_QSEG  (KK * 32 * 8)           // 4096 (one kbuf or one stack segment)
#define SZ_WARP  (4 * SZ_QSEG)           // kbuf0,kbuf1,stk0,stk1 = 16384
#define OFF_RC   SZ_T
#define OFF_W    (SZ_T + SZ_RC)
#define SMEM_TOTAL (OFF_W + WARPS * SZ_WARP)   // 99840

__device__ float g_norms[BB * NN];

__device__ __forceinline__ u64 pk2(float a, float b) {
    u64 r; asm("mov.b64 %0, {%1,%2};" : "=l"(r) : "f"(a), "f"(b)); return r;
}
__device__ __forceinline__ u64 fma2(u64 a, u64 b, u64 c) {
    u64 d; asm("fma.rn.f32x2 %0, %1, %2, %3;" : "=l"(d) : "l"(a), "l"(b), "l"(c));
    return d;
}
__device__ __forceinline__ void up2(u64 v, float& a, float& b) {
    asm("mov.b64 {%0,%1}, %2;" : "=f"(a), "=f"(b) : "l"(v));
}

// Balanced binary tree sum, XLA warp-shfl grouping (stride 16,8,4,2,1).
__device__ __forceinline__ float tree32(float t[32]) {
    #pragma unroll
    for (int off = 16; off >= 1; off >>= 1)
        #pragma unroll
        for (int i = 0; i < off; ++i)
            t[i] = __fadd_rn(t[i], t[i + off]);
    return t[0];
}

// Branch-free insert into ascending sorted k[0..15]; UINT64_MAX is a no-op.
__device__ __forceinline__ void ins16(u64 (&k)[KK], u64 nk) {
    #pragma unroll
    for (int s = KK - 1; s >= 1; --s) {
        u64 mn = (nk < k[s]) ? nk : k[s];
        k[s] = (k[s-1] > mn) ? k[s-1] : mn;
    }
    k[0] = (nk < k[0]) ? nk : k[0];
}

// threshold distance (float) from the worst kept key; sentinel -> +inf
__device__ __forceinline__ float thr_of(u64 wk) {
    u32 hi = (u32)(wk >> 32) ^ 0x80000000u;
    hi = hi < 0x7f800000u ? hi : 0x7f800000u;
    return __uint_as_float(hi);
}

__global__ void norms_kernel(const float* __restrict__ points) {
    int idx = blockIdx.x * blockDim.x + threadIdx.x;
    if (idx >= BB * NN) return;
    const float4* cp = (const float4*)(points + (size_t)idx * DD);
    float x[DD];
    #pragma unroll
    for (int j4 = 0; j4 < DD / 4; ++j4) {
        float4 v = __ldg(cp + j4);
        x[j4*4+0] = __fmul_rn(v.x, v.x);
        x[j4*4+1] = __fmul_rn(v.y, v.y);
        x[j4*4+2] = __fmul_rn(v.z, v.z);
        x[j4*4+3] = __fmul_rn(v.w, v.w);
    }
    g_norms[idx] = tree32(x);
}

// Drain lane's stack entries into its smem-resident sorted top-16.
__device__ __forceinline__ void drain(u64* stk, u64* kbuf, int lane,
                                      int& cnt, float& wq) {
    unsigned mx = __reduce_max_sync(0xffffffffu, (unsigned)cnt);
    if (mx == 0) return;
    u64 k[KK];
    #pragma unroll
    for (int i = 0; i < KK; ++i) k[i] = kbuf[i * 32 + lane];
    for (unsigned e = 0; e < mx; ++e) {
        u64 v = (e < (unsigned)cnt) ? stk[e * 32 + lane] : ~0ull;
        ins16(k, v);
    }
    #pragma unroll
    for (int i = 0; i < KK; ++i) kbuf[i * 32 + lane] = k[i];
    cnt = 0;
    wq = thr_of(k[KK - 1]);
}

// popc-prefix predicated push of up-to-8 passing candidates (no serial chain)
__device__ __forceinline__ void push8(u64* stk, int lane, int& cnt,
                                      const float (&d)[8], int gi, float wq,
                                      int nq, u64* kbuf, float& wqr) {
    const unsigned FULL = 0xffffffffu;
    u32 pm = 0;
    #pragma unroll
    for (int t = 0; t < 8; ++t) pm |= (d[t] <= wq) ? (1u << t) : 0u;
    u32 diff = (u32)(nq - gi);
    if (diff < 8u) pm &= ~(1u << diff);        // exclude self by identity
    if (__any_sync(FULL, pm)) {
        #pragma unroll
        for (int t = 0; t < 8; ++t) {
            if (pm & (1u << t)) {
                int pos = cnt + __popc(pm & ((1u << t) - 1u));
                u32 h = __float_as_uint(d[t]) | 0x80000000u;
                stk[pos * 32 + lane] = ((u64)h << 32) | (u32)(gi + t);
            }
        }
        cnt += __popc(pm);
        if (__any_sync(FULL, cnt > CAP - 8))
            drain(stk, kbuf, lane, cnt, wqr);
    }
}

__global__ __launch_bounds__(THREADS, 2)
void knn_select_kernel(const float* __restrict__ points,
                       const float* __restrict__ features,
                       float* __restrict__ out)
{
    extern __shared__ char smem_raw[];
    float (*s_t)[TST] = (float(*)[TST])smem_raw;
    float* s_rc = (float*)(smem_raw + OFF_RC);

    const int lane = threadIdx.x & 31;
    const int warp = threadIdx.x >> 5;
    const int b    = blockIdx.x >> 4;             // 16 CTAs per batch
    const int q0b  = (blockIdx.x & 15) * QPC;
    const int nq0  = q0b + warp * 32 + lane;
    const int nq1  = nq0 + 128;

    char* wbase = smem_raw + OFF_W + warp * SZ_WARP;
    u64* kbuf0 = (u64*)(wbase);
    u64* kbuf1 = (u64*)(wbase + SZ_QSEG);
    u64* stk0  = (u64*)(wbase + 2 * SZ_QSEG);
    u64* stk1  = (u64*)(wbase + 3 * SZ_QSEG);

    const float* pb = points   + (size_t)b * NN * DD;
    const float* fb = features + (size_t)b * NN * CC;

    // init smem k-lists to sentinel
    #pragma unroll
    for (int i = 0; i < KK; ++i) {
        kbuf0[i * 32 + lane] = ~0ull;
        kbuf1[i * 32 + lane] = ~0ull;
    }

    // ---- both query points: packed u64 duplicates + rq (tree32, ref order) ----
    u64 qd0[DD], qd1[DD];
    float rq0, rq1;
    {
        float x[DD];
        const float4* qp = (const float4*)(pb + (size_t)nq0 * DD);
        #pragma unroll
        for (int j4 = 0; j4 < DD / 4; ++j4) {
            float4 v = __ldg(qp + j4);
            qd0[j4*4+0] = pk2(v.x, v.x); qd0[j4*4+1] = pk2(v.y, v.y);
            qd0[j4*4+2] = pk2(v.z, v.z); qd0[j4*4+3] = pk2(v.w, v.w);
            x[j4*4+0] = __fmul_rn(v.x, v.x); x[j4*4+1] = __fmul_rn(v.y, v.y);
            x[j4*4+2] = __fmul_rn(v.z, v.z); x[j4*4+3] = __fmul_rn(v.w, v.w);
        }
        rq0 = tree32(x);
        qp = (const float4*)(pb + (size_t)nq1 * DD);
        #pragma unroll
        for (int j4 = 0; j4 < DD / 4; ++j4) {
            float4 v = __ldg(qp + j4);
            qd1[j4*4+0] = pk2(v.x, v.x); qd1[j4*4+1] = pk2(v.y, v.y);
            qd1[j4*4+2] = pk2(v.z, v.z); qd1[j4*4+3] = pk2(v.w, v.w);
            x[j4*4+0] = __fmul_rn(v.x, v.x); x[j4*4+1] = __fmul_rn(v.y, v.y);
            x[j4*4+2] = __fmul_rn(v.z, v.z); x[j4*4+3] = __fmul_rn(v.w, v.w);
        }
        rq1 = tree32(x);
    }

    float wq0 = __int_as_float(0x7f800000), wq1 = __int_as_float(0x7f800000);
    int cnt0 = 0, cnt1 = 0;

    for (int tile = 0; tile < NTILES; ++tile) {
        __syncthreads();
        {
            const float4* src = (const float4*)(pb + (size_t)tile * TS * DD);
            #pragma unroll
            for (int it = 0; it < (TS * DD / 4) / THREADS; ++it) {   // 16
                int v  = threadIdx.x + it * THREADS;
                int c  = v >> 3;
                int j0 = (v & 7) << 2;
                float4 p4 = src[v];
                s_t[j0+0][c] = p4.x;
                s_t[j0+1][c] = p4.y;
                s_t[j0+2][c] = p4.z;
                s_t[j0+3][c] = p4.w;
            }
            if (threadIdx.x < TS / 4)
                *(float4*)&s_rc[threadIdx.x * 4] =
                    *(const float4*)&g_norms[b * NN + tile * TS + threadIdx.x * 4];
        }
        __syncthreads();

        #pragma unroll 1
        for (int c8 = 0; c8 < TS; c8 += 8) {
            // ---- 8 candidates x 2 queries: 8 packed FMA chains (ascending j) ----
            u64 acc[8];
            #pragma unroll
            for (int i = 0; i < 8; ++i) acc[i] = 0ull;
            #pragma unroll
            for (int j = 0; j < DD; ++j) {
                const ulonglong2* row = (const ulonglong2*)&s_t[j][c8];
                ulonglong2 pA = row[0], pB = row[1];
                acc[0] = fma2(qd0[j], pA.x, acc[0]);
                acc[1] = fma2(qd0[j], pA.y, acc[1]);
                acc[2] = fma2(qd0[j], pB.x, acc[2]);
                acc[3] = fma2(qd0[j], pB.y, acc[3]);
                acc[4] = fma2(qd1[j], pA.x, acc[4]);
                acc[5] = fma2(qd1[j], pA.y, acc[5]);
                acc[6] = fma2(qd1[j], pB.x, acc[6]);
                acc[7] = fma2(qd1[j], pB.y, acc[7]);
            }
            const int gi = tile * TS + c8;
            float rc[8];
            {
                float4 r0 = *(const float4*)&s_rc[c8];
                float4 r1 = *(const float4*)&s_rc[c8 + 4];
                rc[0]=r0.x; rc[1]=r0.y; rc[2]=r0.z; rc[3]=r0.w;
                rc[4]=r1.x; rc[5]=r1.y; rc[6]=r1.z; rc[7]=r1.w;
            }

            // D = fl(fl(rq - 2m) + rc); FFMA(-2,m,rq) == fl(rq - fl(2m)) bitwise
            float d0[8], d1[8];
            #pragma unroll
            for (int p = 0; p < 4; ++p) {
                float a, b_;
                up2(acc[p], a, b_);
                d0[2*p]   = __fadd_rn(__fmaf_rn(-2.f, a,  rq0), rc[2*p]);
                d0[2*p+1] = __fadd_rn(__fmaf_rn(-2.f, b_, rq0), rc[2*p+1]);
                up2(acc[4 + p], a, b_);
                d1[2*p]   = __fadd_rn(__fmaf_rn(-2.f, a,  rq1), rc[2*p]);
                d1[2*p+1] = __fadd_rn(__fmaf_rn(-2.f, b_, rq1), rc[2*p+1]);
            }

            push8(stk0, lane, cnt0, d0, gi, wq0, nq0, kbuf0, wq0);
            push8(stk1, lane, cnt1, d1, gi, wq1, nq1, kbuf1, wq1);
        }
    }

    // final drains: kbuf holds sorted top-16 by (dist, idx) = reference order
    drain(stk0, kbuf0, lane, cnt0, wq0);
    drain(stk1, kbuf1, lane, cnt1, wq1);
    __syncwarp();

    // publish indices into stk0 region (now dead): si[qq][kk], qq in [0,64)
    int* si = (int*)stk0;
    #pragma unroll
    for (int kk = 0; kk < KK; ++kk) {
        si[lane * KK + kk]        = (int)(u32)kbuf0[kk * 32 + lane];
        si[(32 + lane) * KK + kk] = (int)(u32)kbuf1[kk * 32 + lane];
    }
    __syncwarp();

    // ---- gather + write: 2 contiguous channels per lane, 64-bit accesses ----
    const int l2 = lane * 2;
    for (int qq = 0; qq < 64; ++qq) {
        int n = q0b + ((qq >> 5) << 7) + warp * 32 + (qq & 31);
        float2 c = *(const float2*)(fb + (size_t)n * CC + l2);
        float* ob = out + (size_t)(b * NN + n) * KK * (2 * CC);
        #pragma unroll
        for (int kk = 0; kk < KK; ++kk) {
            int nbv = si[qq * KK + kk];
            float2 g = *(const float2*)(fb + (size_t)nbv * CC + l2);
            float* orow = ob + kk * (2 * CC);
            __stcs((float2*)(orow + l2), g);
            __stcs((float2*)(orow + 64 + l2), make_float2(g.x - c.x, g.y - c.y));
        }
    }
}

extern "C" void kernel_launch(void* const* d_in, const int* in_sizes, int n_in,
                              void* d_out, int out_size) {
    const float* points   = (const float*)d_in[0];
    const float* features = (const float*)d_in[1];
    float* out = (float*)d_out;
    (void)in_sizes; (void)n_in; (void)out_size;
    cudaFuncSetAttribute(knn_select_kernel,
                         cudaFuncAttributeMaxDynamicSharedMemorySize, SMEM_TOTAL);
    norms_kernel<<<(BB * NN + 255) / 256, 256>>>(points);
    knn_select_kernel<<<BB * (NN / QPC), THREADS, SMEM_TOTAL>>>(points, features, out);
}